// round 14
// baseline (speedup 1.0000x reference)
#include <cuda_runtime.h>
#include <cuda_bf16.h>
#include <cuda_fp16.h>
#include <math.h>
#include <stdint.h>

#define SEQ 1024
#define DM  1024
#define NH  16
#define HD  64
#define NB  2
#define GK  1024
#define L2E 1.4426950408889634f

__device__ __half g_xh[NB*SEQ*DM];
__device__ __half g_vbrelh[NH*2*SEQ + 32];
__device__ __nv_bfloat16 g_qhi[NB*NH*SEQ*HD], g_qlo[NB*NH*SEQ*HD];
__device__ __nv_bfloat16 g_khi[NB*NH*SEQ*HD], g_klo[NB*NH*SEQ*HD];
__device__ __half g_vth[NB*NH*HD*SEQ];
__device__ __nv_bfloat16 g_poshi[(2*SEQ+1)*HD], g_poslo[(2*SEQ+1)*HD];
__device__ __nv_bfloat16 g_wqhi[DM*GK], g_wqlo[DM*GK];
__device__ __half        g_wvhi[DM*GK], g_wvlo[DM*GK];
__device__ __half        g_wohi[DM*GK], g_wolo[DM*GK];

__device__ __forceinline__ uint32_t smem_u32(const void* p) {
    uint32_t a;
    asm("{ .reg .u64 t; cvta.to.shared.u64 t, %1; cvt.u32.u64 %0, t; }" : "=r"(a) : "l"(p));
    return a;
}
__device__ __forceinline__ void ldsm_x4(uint32_t (&r)[4], uint32_t addr) {
    asm volatile("ldmatrix.sync.aligned.m8n8.x4.shared.b16 {%0,%1,%2,%3}, [%4];"
        : "=r"(r[0]), "=r"(r[1]), "=r"(r[2]), "=r"(r[3]) : "r"(addr));
}
__device__ __forceinline__ void mma_bf16(float (&d)[4], const uint32_t (&a)[4],
                                         uint32_t b0, uint32_t b1) {
    asm volatile("mma.sync.aligned.m16n8k16.row.col.f32.bf16.bf16.f32 "
        "{%0,%1,%2,%3}, {%4,%5,%6,%7}, {%8,%9}, {%0,%1,%2,%3};"
        : "+f"(d[0]), "+f"(d[1]), "+f"(d[2]), "+f"(d[3])
        : "r"(a[0]), "r"(a[1]), "r"(a[2]), "r"(a[3]), "r"(b0), "r"(b1));
}
__device__ __forceinline__ void mma_f16(float (&d)[4], const uint32_t (&a)[4],
                                        uint32_t b0, uint32_t b1) {
    asm volatile("mma.sync.aligned.m16n8k16.row.col.f32.f16.f16.f32 "
        "{%0,%1,%2,%3}, {%4,%5,%6,%7}, {%8,%9}, {%0,%1,%2,%3};"
        : "+f"(d[0]), "+f"(d[1]), "+f"(d[2]), "+f"(d[3])
        : "r"(a[0]), "r"(a[1]), "r"(a[2]), "r"(a[3]), "r"(b0), "r"(b1));
}
__device__ __forceinline__ void cpa16(uint32_t dst, const void* src) {
    asm volatile("cp.async.cg.shared.global [%0], [%1], 16;" :: "r"(dst), "l"(src));
}
#define CP_COMMIT() asm volatile("cp.async.commit_group;" ::: "memory")
#define CP_WAIT0()  asm volatile("cp.async.wait_group 0;" ::: "memory")

__device__ __forceinline__ void split_sts(float4 v, char* hi, char* lo) {
    __nv_bfloat162 h01 = __floats2bfloat162_rn(v.x, v.y);
    __nv_bfloat162 h23 = __floats2bfloat162_rn(v.z, v.w);
    float2 f01 = __bfloat1622float2(h01);
    float2 f23 = __bfloat1622float2(h23);
    __nv_bfloat162 l01 = __floats2bfloat162_rn(v.x - f01.x, v.y - f01.y);
    __nv_bfloat162 l23 = __floats2bfloat162_rn(v.z - f23.x, v.w - f23.y);
    *(uint2*)hi = make_uint2(*(uint32_t*)&h01, *(uint32_t*)&h23);
    *(uint2*)lo = make_uint2(*(uint32_t*)&l01, *(uint32_t*)&l23);
}
__device__ __forceinline__ void split_sts_h(float4 v, char* hi, char* lo) {
    __half2 h01 = __floats2half2_rn(v.x, v.y);
    __half2 h23 = __floats2half2_rn(v.z, v.w);
    float2 f01 = __half22float2(h01);
    float2 f23 = __half22float2(h23);
    __half2 l01 = __floats2half2_rn(v.x - f01.x, v.y - f01.y);
    __half2 l23 = __floats2half2_rn(v.z - f23.x, v.w - f23.y);
    *(uint2*)hi = make_uint2(*(uint32_t*)&h01, *(uint32_t*)&h23);
    *(uint2*)lo = make_uint2(*(uint32_t*)&l01, *(uint32_t*)&l23);
}
__device__ __forceinline__ uint32_t packsplit(float a, float b, uint32_t& lo) {
    __nv_bfloat162 hh = __floats2bfloat162_rn(a, b);
    float2 ff = __bfloat1622float2(hh);
    __nv_bfloat162 ll = __floats2bfloat162_rn(a - ff.x, b - ff.y);
    lo = *(uint32_t*)&ll;
    return *(uint32_t*)&hh;
}
__device__ __forceinline__ void split1(float v, __nv_bfloat16& hi, __nv_bfloat16& lo) {
    hi = __float2bfloat16_rn(v);
    lo = __float2bfloat16_rn(v - __bfloat162float(hi));
}

// ---------------- front prep: pos + vbrel(fp16) + K + weight splits ----------------
__global__ __launch_bounds__(512) void front_prep(
    const float* __restrict__ keyg,
    const float* __restrict__ Wq, const float* __restrict__ Wv,
    const float* __restrict__ Wo, const float* __restrict__ vbias)
{
    __shared__ float ps[1024], vbs[1024];
    const int tid = threadIdx.x;
    const int gid = blockIdx.x * 512 + tid;
    const int NT = 256 * 512;

    if (blockIdx.x < 128) {
        const int pid = blockIdx.x;
        for (int i = tid; i < 1024; i += 512) vbs[i] = vbias[i];
        {
            const int li = tid >> 5, j = tid & 31;
            const int l = pid * 16 + li;
            float p = (float)(l - SEQ);
            const double negc = -log(10000.0) / 31.0;
            float ang = p * (float)exp((double)j * negc);
            float s = (float)sin((double)ang), c = (float)cos((double)ang);
            ps[li*64 + j] = s; ps[li*64 + j + 32] = c;
            __nv_bfloat16 hh, ll;
            split1(s, hh, ll); g_poshi[l*64+j] = hh;      g_poslo[l*64+j] = ll;
            split1(c, hh, ll); g_poshi[l*64+j+32] = hh;   g_poslo[l*64+j+32] = ll;
        }
        __syncthreads();
        if (tid < 256) {
            const int li = tid >> 4, h = tid & 15;
            float sum = 0.f;
            #pragma unroll 8
            for (int d = 0; d < 64; d++) sum = fmaf(vbs[h*64+d], ps[li*64+d], sum);
            g_vbrelh[h*2048 + pid*16 + li] = __float2half_rn(sum);
        }
    }

    // key -> (b,h,s,d) bf16 hi/lo
    for (int i = gid; i < 524288; i += NT) {
        float4 v = ((const float4*)keyg)[i];
        int cc = i & 255, ss = (i >> 8) & 1023, bb = i >> 18;
        size_t o = ((size_t)(bb*NH + (cc >> 4))*SEQ + ss)*HD + (cc & 15)*4;
        split_sts(v, (char*)(g_khi + o), (char*)(g_klo + o));
    }
    // weights
    for (int i = gid; i < 262144; i += NT) {
        float4 v = ((const float4*)Wq)[i];
        split_sts(v, (char*)g_wqhi + (size_t)i*8, (char*)g_wqlo + (size_t)i*8);
        v = ((const float4*)Wv)[i];
        split_sts_h(v, (char*)g_wvhi + (size_t)i*8, (char*)g_wvlo + (size_t)i*8);
        v = ((const float4*)Wo)[i];
        split_sts_h(v, (char*)g_wohi + (size_t)i*8, (char*)g_wolo + (size_t)i*8);
    }
}

// ---------------- GEMM cores ----------------
#define TSTRIDE 40
#define TILE_B  (128 * TSTRIDE * 2)
#define BUF_B   (4 * TILE_B)
#define HG_SMEM (2 * BUF_B)
#define BUF_H   (3 * TILE_B)
#define OG_SMEM (2 * BUF_H)

// bf16 3-term: A fp32 in-core split, B pre-split async
__device__ __forceinline__ void gemm3_hybA(
    const float* __restrict__ Af,
    const __nv_bfloat16* __restrict__ Bh, const __nv_bfloat16* __restrict__ Bl,
    char* smraw, uint32_t sbase, int tid, int lane, int wm, int wn, float acc[2][4][4])
{
    const int lr = tid >> 2, lc = (tid & 3) * 8;
    const uint32_t bo = (uint32_t)(lr*TSTRIDE + lc) * 2;
    const int a_r = lane & 15, a_c = (lane >> 4) << 3;
    const int b_r = (lane & 7) + ((lane & 16) >> 1), b_c = lane & 8;

    float4 av[2];
    {
        const size_t o = (size_t)lr*GK + lc;
        cpa16(sbase + 2*TILE_B + bo, Bh + o);
        cpa16(sbase + 3*TILE_B + bo, Bl + o);
        CP_COMMIT();
        av[0] = *(const float4*)(Af + o);
        av[1] = *(const float4*)(Af + o + 4);
        split_sts(av[0], smraw + bo, smraw + TILE_B + bo);
        split_sts(av[1], smraw + bo + 8, smraw + TILE_B + bo + 8);
    }
    CP_WAIT0(); __syncthreads();

    for (int kt = 0; kt < 32; kt++) {
        if (kt < 31) {
            const size_t o = (size_t)lr*GK + (kt+1)*32 + lc;
            const uint32_t db = sbase + ((kt+1)&1)*BUF_B + bo;
            cpa16(db + 2*TILE_B, Bh + o);
            cpa16(db + 3*TILE_B, Bl + o);
            CP_COMMIT();
            av[0] = *(const float4*)(Af + o);
            av[1] = *(const float4*)(Af + o + 4);
        }
        const uint32_t base = sbase + (kt & 1) * BUF_B;
        #pragma unroll
        for (int kk = 0; kk < 2; kk++) {
            const int koff = kk * 16;
            uint32_t ah[2][4], al[2][4];
            #pragma unroll
            for (int i = 0; i < 2; i++) {
                const uint32_t off = (uint32_t)(((wm*32 + i*16 + a_r)*TSTRIDE + koff + a_c) * 2);
                ldsm_x4(ah[i], base + off);
                ldsm_x4(al[i], base + TILE_B + off);
            }
            uint32_t bh[2][4], bl[2][4];
            #pragma unroll
            for (int p = 0; p < 2; p++) {
                const uint32_t off = (uint32_t)(((wn*32 + p*16 + b_r)*TSTRIDE + koff + b_c) * 2);
                ldsm_x4(bh[p], base + 2*TILE_B + off);
                ldsm_x4(bl[p], base + 3*TILE_B + off);
            }
            #pragma unroll
            for (int i = 0; i < 2; i++)
                #pragma unroll
                for (int j = 0; j < 4; j++) {
                    const int p = j >> 1, s = (j & 1) * 2;
                    mma_bf16(acc[i][j], ah[i], bh[p][s], bh[p][s+1]);
                    mma_bf16(acc[i][j], ah[i], bl[p][s], bl[p][s+1]);
                    mma_bf16(acc[i][j], al[i], bh[p][s], bh[p][s+1]);
                }
        }
        if (kt < 31) {
            char* db = smraw + ((kt+1)&1)*BUF_B;
            split_sts(av[0], db + bo, db + TILE_B + bo);
            split_sts(av[1], db + bo + 8, db + TILE_B + bo + 8);
            CP_WAIT0(); __syncthreads();
        }
    }
}

// fp16 2-term: A fp32 in-core cvt (AH=false) or fp16 async (AH=true), B pre-split async
template<bool AH>
__device__ __forceinline__ void gemm2h_core(
    const void* __restrict__ Ap,
    const __half* __restrict__ Bh, const __half* __restrict__ Bl,
    char* smraw, uint32_t sbase, int tid, int lane, int wm, int wn, float acc[2][4][4])
{
    const int lr = tid >> 2, lc = (tid & 3) * 8;
    const uint32_t bo = (uint32_t)(lr*TSTRIDE + lc) * 2;
    const int a_r = lane & 15, a_c = (lane >> 4) << 3;
    const int b_r = (lane & 7) + ((lane & 16) >> 1), b_c = lane & 8;

    float4 av[2];
    {
        const size_t o = (size_t)lr*GK + lc;
        cpa16(sbase + TILE_B + bo,   Bh + o);
        cpa16(sbase + 2*TILE_B + bo, Bl + o);
        if (AH) cpa16(sbase + bo, (const __half*)Ap + o);
        CP_COMMIT();
        if (!AH) {
            av[0] = *(const float4*)((const float*)Ap + o);
            av[1] = *(const float4*)((const float*)Ap + o + 4);
            __half2 h0 = __floats2half2_rn(av[0].x, av[0].y);
            __half2 h1 = __floats2half2_rn(av[0].z, av[0].w);
            __half2 h2 = __floats2half2_rn(av[1].x, av[1].y);
            __half2 h3 = __floats2half2_rn(av[1].z, av[1].w);
            *(uint4*)(smraw + bo) = make_uint4(*(uint32_t*)&h0, *(uint32_t*)&h1,
                                               *(uint32_t*)&h2, *(uint32_t*)&h3);
        }
    }
    CP_WAIT0(); __syncthreads();

    for (int kt = 0; kt < 32; kt++) {
        if (kt < 31) {
            const size_t o = (size_t)lr*GK + (kt+1)*32 + lc;
            const uint32_t db = sbase + ((kt+1)&1)*BUF_H + bo;
            cpa16(db + TILE_B,   Bh + o);
            cpa16(db + 2*TILE_B, Bl + o);
            if (AH) cpa16(db, (const __half*)Ap + o);
            CP_COMMIT();
            if (!AH) {
                av[0] = *(const float4*)((const float*)Ap + o);
                av[1] = *(const float4*)((const float*)Ap + o + 4);
            }
        }
        const uint32_t base = sbase + (kt & 1) * BUF_H;
        #pragma unroll
        for (int kk = 0; kk < 2; kk++) {
            const int koff = kk * 16;
            uint32_t af[2][4];
            #pragma unroll
            for (int i = 0; i < 2; i++) {
                const uint32_t off = (uint32_t)(((wm*32 + i*16 + a_r)*TSTRIDE + koff + a_c) * 2);
                ldsm_x4(af[i], base + off);
            }
            uint32_t bh[2][4], bl[2][4];
            #pragma unroll
            for (int p = 0; p < 2; p++) {
                const uint32_t off = (uint32_t)(((wn*32 + p*16 + b_r)*TSTRIDE + koff + b_c) * 2);
                ldsm_x4(bh[p], base + TILE_B + off);
                ldsm_x4(bl[p], base + 2*TILE_B + off);
            }
            #pragma unroll
            for (int i = 0; i < 2; i++)
                #pragma unroll
                for (int j = 0; j < 4; j++) {
                    const int p = j >> 1, s = (j & 1) * 2;
                    mma_f16(acc[i][j], af[i], bh[p][s], bh[p][s+1]);
                    mma_f16(acc[i][j], af[i], bl[p][s], bl[p][s+1]);
                }
        }
        if (kt < 31) {
            if (!AH) {
                char* db = smraw + ((kt+1)&1)*BUF_H;
                __half2 h0 = __floats2half2_rn(av[0].x, av[0].y);
                __half2 h1 = __floats2half2_rn(av[0].z, av[0].w);
                __half2 h2 = __floats2half2_rn(av[1].x, av[1].y);
                __half2 h3 = __floats2half2_rn(av[1].z, av[1].w);
                *(uint4*)(db + bo) = make_uint4(*(uint32_t*)&h0, *(uint32_t*)&h1,
                                                *(uint32_t*)&h2, *(uint32_t*)&h3);
            }
            CP_WAIT0(); __syncthreads();
        }
    }
}

// z=0: Q proj; z=1: V proj (transposed fp16 out)
__global__ __launch_bounds__(512) void qv_gemm512(
    const float* __restrict__ query, const float* __restrict__ value,
    const float* __restrict__ bq, const float* __restrict__ bv)
{
    extern __shared__ __align__(16) char smraw[];
    const int tid = threadIdx.x, lane = tid & 31, wid = tid >> 5;
    const int wm = wid & 3, wn = wid >> 2;
    const int row0 = blockIdx.y * 128, col0 = blockIdx.x * 128;
    const int z = blockIdx.z;

    float acc[2][4][4];
    #pragma unroll
    for (int i = 0; i < 2; i++)
        #pragma unroll
        for (int j = 0; j < 4; j++)
            #pragma unroll
            for (int c = 0; c < 4; c++) acc[i][j][c] = 0.f;

    const int grp = lane >> 2, qid = lane & 3;
    const uint32_t sb = smem_u32(smraw);

    if (z == 0) {
        gemm3_hybA(query + (size_t)row0*GK,
                   g_wqhi + (size_t)col0*GK, g_wqlo + (size_t)col0*GK,
                   smraw, sb, tid, lane, wm, wn, acc);
        #pragma unroll
        for (int j = 0; j < 4; j++) {
            const int col = col0 + wn*32 + j*8 + qid*2;
            const float2 bj = *(const float2*)(bq + col);
            const int h = col >> 6, d = col & 63;
            #pragma unroll
            for (int i = 0; i < 2; i++) {
                const int row = row0 + wm*32 + i*16 + grp;
                const int b = row >> 10, s = row & 1023;
                size_t o = (((size_t)(b*NH + h))*SEQ + s)*HD + d;
                uint32_t lo0, lo1;
                uint32_t hi0 = packsplit(acc[i][j][0]+bj.x, acc[i][j][1]+bj.y, lo0);
                uint32_t hi1 = packsplit(acc[i][j][2]+bj.x, acc[i][j][3]+bj.y, lo1);
                *(uint32_t*)(g_qhi + o) = hi0;        *(uint32_t*)(g_qlo + o) = lo0;
                *(uint32_t*)(g_qhi + o + 8*HD) = hi1; *(uint32_t*)(g_qlo + o + 8*HD) = lo1;
            }
        }
    } else {
        gemm2h_core<false>(value + (size_t)row0*GK,
                           g_wvhi + (size_t)col0*GK, g_wvlo + (size_t)col0*GK,
                           smraw, sb, tid, lane, wm, wn, acc);
        #pragma unroll
        for (int j = 0; j < 4; j++) {
            const int col = col0 + wn*32 + j*8 + qid*2;
            const float2 bj = *(const float2*)(bv + col);
            const int h = col >> 6, d = col & 63;
            #pragma unroll
            for (int i = 0; i < 2; i++) {
                const int row = row0 + wm*32 + i*16 + grp;
                const int b = row >> 10, s = row & 1023;
                size_t o = (((size_t)(b*NH + h))*HD + d)*SEQ + s;
                g_vth[o]        = __float2half_rn(acc[i][j][0]+bj.x);
                g_vth[o+SEQ]    = __float2half_rn(acc[i][j][1]+bj.y);
                g_vth[o+8]      = __float2half_rn(acc[i][j][2]+bj.x);
                g_vth[o+SEQ+8]  = __float2half_rn(acc[i][j][3]+bj.y);
            }
        }
    }
}

__global__ __launch_bounds__(512) void o_gemm512(
    const float* __restrict__ bias, float* __restrict__ C)
{
    extern __shared__ __align__(16) char smraw[];
    const int tid = threadIdx.x, lane = tid & 31, wid = tid >> 5;
    const int wm = wid & 3, wn = wid >> 2;
    const int row0 = blockIdx.y * 128, col0 = blockIdx.x * 128;

    float acc[2][4][4];
    #pragma unroll
    for (int i = 0; i < 2; i++)
        #pragma unroll
        for (int j = 0; j < 4; j++)
            #pragma unroll
            for (int c = 0; c < 4; c++) acc[i][j][c] = 0.f;

    gemm2h_core<true>(g_xh + (size_t)row0*GK,
                      g_wohi + (size_t)col0*GK, g_wolo + (size_t)col0*GK,
                      smraw, smem_u32(smraw), tid, lane, wm, wn, acc);

    const int grp = lane >> 2, qid = lane & 3;
    #pragma unroll
    for (int j = 0; j < 4; j++) {
        const int col = col0 + wn*32 + j*8 + qid*2;
        const float2 bj = *(const float2*)(bias + col);
        #pragma unroll
        for (int i = 0; i < 2; i++) {
            const int row = row0 + wm*32 + i*16 + grp;
            *(float2*)(C + (size_t)row*DM + col)     = make_float2(acc[i][j][0]+bj.x, acc[i][j][1]+bj.y);
            *(float2*)(C + (size_t)(row+8)*DM + col) = make_float2(acc[i][j][2]+bj.x, acc[i][j][3]+bj.y);
        }
    }
}

// --------- pipelined tensor-core fused attention ---------
#define RSTR 130
#define S0OFF 32768u
#define S1OFF 65536u
#define ROFF  98304
#define RSLOT 66560
#define VBOFF 231424u
#define A_SMEM 231936

__device__ __forceinline__ void stage_rows_async(
    uint32_t sb, uint32_t so, int tid,
    const __nv_bfloat16* hp, const __nv_bfloat16* lp)
{
    #pragma unroll
    for (int r = 0; r < 4; r++) {
        int idx = tid + r*256, row = idx >> 3, c = idx & 7;
        uint32_t off = so + row*128 + ((c ^ (row & 7)) << 4);
        cpa16(sb + off,         (const char*)hp + idx*16);
        cpa16(sb + off + 16384, (const char*)lp + idx*16);
    }
}
// vbrel band: scalar half loads (src is only 2B-aligned — NO cp.async here)
__device__ __forceinline__ void stage_vb_scalar(char* sm, int slot, int tid, const __half* src) {
    if (tid < 128) ((__half*)(sm + VBOFF))[slot*128 + tid] = __ldg(src + tid);
}
__device__ __forceinline__ void stage_vt_async(
    uint32_t sb, uint32_t so, int tid, const __half* hp, int k0)
{
    #pragma unroll
    for (int r = 0; r < 4; r++) {
        int idx = tid + r*256, d = idx >> 4, c = idx & 15;
        uint32_t off = so + d*256 + ((c ^ (d & 7)) << 4);
        cpa16(sb + off, (const char*)(hp + (size_t)d*SEQ + k0) + c*16);
    }
}

__device__ __forceinline__ void rgemm_band(
    uint32_t sb, uint32_t so, int lane, int wm, int wn, int grp, int qid,
    float* R, const __half* vbs)
{
    float rc[4][4][4];
    #pragma unroll
    for (int i = 0; i < 4; i++)
        #pragma unroll
        for (int j = 0; j < 4; j++) { rc[i][j][0]=0;rc[i][j][1]=0;rc[i][j][2]=0;rc[i][j][3]=0; }
    #pragma unroll
    for (int kb = 0; kb < 4; kb++) {
        uint32_t ah[4][4], al[4][4];
        #pragma unroll
        for (int i = 0; i < 4; i++) {
            uint32_t ao = (uint32_t)((wm*64 + i*16 + (lane&15))*128
                         + (((kb*2 + (lane>>4)) ^ (lane&7)) << 4));
            ldsm_x4(ah[i], sb + ao);
            ldsm_x4(al[i], sb + 16384 + ao);
        }
        uint32_t bh2[2][4], bl2[2][4];
        #pragma unroll
        for (int jp = 0; jp < 2; jp++) {
            uint32_t bo = (uint32_t)((wn*32 + jp*16 + (lane&7) + ((lane&16)>>1))*128
                         + (((kb*2 + ((lane&8)>>3)) ^ (lane&7)) << 4));
            ldsm_x4(bh2[jp], sb + so + bo);
            ldsm_x4(bl2[jp], sb + so + 16384 + bo);
        }
        #pragma unroll
        for (int i = 0; i < 4; i++)
            #pragma unroll
            for (int j = 0; j < 4; j++) {
                const int jp = j >> 1, s = (j & 1)*2;
                mma_bf16(rc[i][j], ah[i], bh2[jp][s], bh2[jp][s+1]);
                mma_bf16(rc[i][j], ah[i], bl2[jp][s], bl2[jp][s+1]);
                mma_bf16(rc[i][j], al[i], bh2[jp][s], bh2[jp][s+1]);
            }
    }
    #pragma unroll
    for (int i = 0; i < 4; i++) {
        const int u = wm*64 + i*16 + grp;
        #pragma unroll
        for (int j = 0; j < 4; j++) {
            const int l = wn*32 + j*8 + qid*2;
            float2 vf = __half22float2(*(const __half2*)(vbs + l));
            *(float2*)&R[u*RSTR + l]     = make_float2(rc[i][j][0]+vf.x, rc[i][j][1]+vf.y);
            *(float2*)&R[(u+8)*RSTR + l] = make_float2(rc[i][j][2]+vf.x, rc[i][j][3]+vf.y);
        }
    }
}

__global__ __launch_bounds__(256, 1) void attn_mma()
{
    extern __shared__ __align__(16) char sm[];
    float* Rb0 = (float*)(sm + ROFF);
    float* Rb1 = (float*)(sm + ROFF + RSLOT);
    const __half* vb0 = (const __half*)(sm + VBOFF);
    const __half* vb1 = (const __half*)(sm + VBOFF + 256);
    const int tid = threadIdx.x, lane = tid & 31, wid = tid >> 5;
    const int grp = lane >> 2, qid = lane & 3;
    const int q0 = blockIdx.x*128, h = blockIdx.y, b = blockIdx.z, bh = b*NH + h;
    const uint32_t sb = smem_u32(sm);
    const int wm = wid & 1, wn = wid >> 1;
    const int u0w = wid*16, r0 = u0w + grp;
    const int lmin0 = SEQ - q0 - 127;
    const __half* vbgh = g_vbrelh + h*2048;
    const __nv_bfloat16* khB = g_khi + (size_t)bh*SEQ*HD;
    const __nv_bfloat16* klB = g_klo + (size_t)bh*SEQ*HD;
    const __half* vhB = g_vth + (size_t)bh*HD*SEQ;

    {   // Q stage (sync, once)
        const uint4* sh = (const uint4*)(g_qhi + ((size_t)bh*SEQ + q0)*HD);
        const uint4* sl = (const uint4*)(g_qlo + ((size_t)bh*SEQ + q0)*HD);
        #pragma unroll
        for (int r = 0; r < 4; r++) {
            int idx = tid + r*256, row = idx >> 3, c = idx & 7;
            int off = row*128 + ((c ^ (row & 7)) << 4);
            *(uint4*)(sm + off) = sh[idx];
            *(uint4*)(sm + 16384 + off) = sl[idx];
        }
    }
    float O[8][4];
    #pragma unroll
    for (int j = 0; j < 8; j++) { O[j][0]=0;O[j][1]=0;O[j][2]=0;O[j][3]=0; }
    float mr0 = -INFINITY, mr1 = -INFINITY, lr0 = 0.f, lr1 = 0.f;

    // prologue
    stage_rows_async(sb, S0OFF, tid, g_poshi + (size_t)lmin0*HD, g_poslo + (size_t)lmin0*HD);
    stage_vb_scalar(sm, 0, tid, vbgh + lmin0);
    CP_COMMIT(); CP_WAIT0(); __syncthreads();

    stage_rows_async(sb, S1OFF, tid, g_poshi + (size_t)(lmin0+128)*HD, g_poslo + (size_t)(lmin0+128)*HD);
    stage_vb_scalar(sm, 1, tid, vbgh + lmin0 + 128);
    CP_COMMIT();
    rgemm_band(sb, S0OFF, lane, wm, wn, grp, qid, Rb0, vb0);
    CP_WAIT0(); __syncthreads();

    stage_rows_async(sb, S0OFF, tid, khB, klB);
    CP_COMMIT();
    rgemm_band(sb, S1OFF, lane, wm, wn, grp, qid, Rb1, vb1);
    CP_WAIT0(); __syncthreads();

    for (int kt = 0; kt < 8; kt++) {
        const int k0 = kt*128;
        const uint32_t kOff = (kt & 1) ? S1OFF : S0OFF;
        const uint32_t vOff = (kt & 1) ? S0OFF : S1OFF;

        if (kt > 0) {
            stage_rows_async(sb, kOff, tid, khB + (size_t)k0*HD, klB + (size_t)k0*HD);
            CP_COMMIT();
            rgemm_band(sb, vOff, lane, wm, wn, grp, qid,
                       ((kt+1) & 1) ? Rb1 : Rb0, ((kt+1) & 1) ? vb1 : vb0);
            CP_WAIT0(); __syncthreads();
        }

        stage_vt_async(sb, vOff, tid, vhB, k0);
        CP_COMMIT();

        float aq[16][4];
        #pragma unroll
        for (int j = 0; j < 16; j++) { aq[j][0]=0;aq[j][1]=0;aq[j][2]=0;aq[j][3]=0; }
        #pragma unroll
        for (int kb = 0; kb < 4; kb++) {
            uint32_t ah[4], al[4];
            uint32_t ao = (uint32_t)((u0w + (lane&15))*128
                         + (((kb*2 + (lane>>4)) ^ (lane&7)) << 4));
            ldsm_x4(ah, sb + ao);
            ldsm_x4(al, sb + 16384 + ao);
            #pragma unroll
            for (int jp = 0; jp < 8; jp++) {
                uint32_t bh4[4], bl4[4];
                uint32_t bo = (uint32_t)((jp*16 + (lane&7) + ((lane&16)>>1))*128
                             + (((kb*2 + ((lane&8)>>3)) ^ (lane&7)) << 4));
                ldsm_x4(bh4, sb + kOff + bo);
                ldsm_x4(bl4, sb + kOff + 16384 + bo);
                #pragma unroll
                for (int jj = 0; jj < 2; jj++) {
                    const int j = jp*2 + jj, s = jj*2;
                    mma_bf16(aq[j], ah, bh4[s], bh4[s+1]);
                    mma_bf16(aq[j], ah, bl4[s], bl4[s+1]);
                    mma_bf16(aq[j], al, bh4[s], bh4[s+1]);
                }
            }
        }

        // V ready + kOff free: stage pos(kt+2)+vb, then softmax->PV unbarriered
        CP_WAIT0(); __syncthreads();
        if (kt < 7) {
            const int l0n = lmin0 + 128*(kt+2);
            stage_rows_async(sb, kOff, tid, g_poshi + (size_t)l0n*HD, g_poslo + (size_t)l0n*HD);
            stage_vb_scalar(sm, kt & 1, tid, vbgh + l0n);
            CP_COMMIT();
        }

        const float* RA  = (kt & 1) ? Rb1 : Rb0;
        const float* RBf = (kt & 1) ? Rb0 : Rb1;
        float m0 = -INFINITY, m1 = -INFINITY;
        #pragma unroll
        for (int j = 0; j < 16; j++) {
            const int w = j*8 + qid*2;
            const int ma = 127 + w - r0, mb = ma - 8;
            aq[j][0] += (ma < 128)   ? RA[r0*RSTR + ma]         : RBf[r0*RSTR + ma - 128];
            aq[j][1] += (ma+1 < 128) ? RA[r0*RSTR + ma + 1]     : RBf[r0*RSTR + ma - 127];
            aq[j][2] += (mb < 128)   ? RA[(r0+8)*RSTR + mb]     : RBf[(r0+8)*RSTR + mb - 128];
            aq[j][3] += (mb+1 < 128) ? RA[(r0+8)*RSTR + mb + 1] : RBf[(r0+8)*RSTR + mb - 127];
            m0 = fmaxf(m0, fmaxf(aq[j][0], aq[j][1]));
            m1 = fmaxf(m1, fmaxf(aq[j][2], aq[j][3]));
        }
        m0 = fmaxf(m0, __shfl_xor_sync(~0u, m0, 1));
        m0 = fmaxf(m0, __shfl_xor_sync(~0u, m0, 2));
        m1 = fmaxf(m1, __shfl_xor_sync(~0u, m1, 1));
        m1 = fmaxf(m1, __shfl_xor_sync(~0u, m1, 2));
        const float mn0 = fmaxf(mr0, m0), mn1 = fmaxf(mr1, m1);
        const float scl0 = __expf(mr0 - mn0), scl1 = __expf(mr1 - mn1);
        mr0 = mn0; mr1 = mn1;

        uint32_t phi[8][4];
        float s0 = 0.f, s1 = 0.f;
        #pragma unroll
        for (int j = 0; j < 16; j++) {
            __half2 hd0 = __floats2half2_rn((aq[j][0]-mn0)*L2E, (aq[j][1]-mn0)*L2E);
            __half2 hd1 = __floats2half2_rn((aq[j][2]-mn1)*L2E, (aq[j][3]-mn1)*L2E);
            uint32_t p0, p1;
            asm("ex2.approx.f16x2 %0, %1;" : "=r"(p0) : "r"(*(uint32_t*)&hd0));
            asm("ex2.approx.f16x2 %0, %1;" : "=r"(p1) : "r"(*(uint32_t*)&hd1));
            const int kk = j >> 1, bs = (j & 1)*2;
            phi[kk][bs]   = p0;
            phi[kk][bs+1] = p1;
            float2 f0 = __half22float2(*(__half2*)&p0);
            float2 f1 = __half22float2(*(__half2*)&p1);
            s0 += f0.x + f0.y; s1 += f1.x + f1.y;
        }
        s0 += __shfl_xor_sync(~0u, s0, 1); s0 += __shfl_xor_sync(~0u, s0, 2);
        s1 += __shfl_xor_sync(~0u, s1, 1); s1 += __shfl_xor_sync(~0u, s1, 2);
        lr0 = lr0*scl0 + s0; lr1 = lr1*scl1 + s1;
        #pragma unroll
        for (int j = 0; j < 8; j++) {
            O[j][0] *= scl0; O[j][1] *= scl0; O[j][2] *= scl1; O[j][3] *= scl1;
        }

        // PV immediately (no barrier)
        #pragma unroll
        for (int kk = 0; kk < 8; kk++) {
            #pragma unroll
            for (int jp = 0; jp < 4; jp++) {
                uint32_t bh4[4];
                uint32_t bo = (uint32_t)((jp*16 + (lane&7) + ((lane&16)>>1))*256
                             + (((kk*2 + ((lane&8)>>3)) ^ (lane&7)) << 4));
                ldsm_x4(bh4, sb + vOff + bo);
                mma_f16(O[jp*2],   phi[kk], bh4[0], bh4[1]);
                mma_f16(O[jp*2+1], phi[kk], bh4[2], bh4[3]);
            }
        }
        if (kt < 7) CP_WAIT0();
        __syncthreads();
    }

    const float i0 = 1.f/lr0, i1 = 1.f/lr1;
    __half* x0 = g_xh + ((size_t)(b*SEQ + q0 + r0))*DM + h*HD;
    __half* x1 = g_xh + ((size_t)(b*SEQ + q0 + r0 + 8))*DM + h*HD;
    #pragma unroll
    for (int j = 0; j < 8; j++) {
        const int col = j*8 + qid*2;
        __half2 o0 = __floats2half2_rn(O[j][0]*i0, O[j][1]*i0);
        __half2 o1 = __floats2half2_rn(O[j][2]*i1, O[j][3]*i1);
        *(__half2*)(x0 + col) = o0;
        *(__half2*)(x1 + col) = o1;
    }
}

// ---------------------------------------------------------------------------
extern "C" void kernel_launch(void* const* d_in, const int* in_sizes, int n_in,
                              void* d_out, int out_size) {
    const float* query  = (const float*)d_in[0];
    const float* key    = (const float*)d_in[1];
    const float* value  = (const float*)d_in[2];
    const float* Wq     = (const float*)d_in[4];
    const float* bq     = (const float*)d_in[5];
    const float* Wv     = (const float*)d_in[6];
    const float* bv     = (const float*)d_in[7];
    const float* Wo     = (const float*)d_in[8];
    const float* bo     = (const float*)d_in[9];
    const float* v_bias = (const float*)d_in[10];
    float* out = (float*)d_out;

    cudaFuncSetAttribute(qv_gemm512, cudaFuncAttributeMaxDynamicSharedMemorySize, HG_SMEM);
    cudaFuncSetAttribute(o_gemm512, cudaFuncAttributeMaxDynamicSharedMemorySize, OG_SMEM);
    cudaFuncSetAttribute(attn_mma, cudaFuncAttributeMaxDynamicSharedMemorySize, A_SMEM);

    front_prep<<<256, 512>>>(key, Wq, Wv, Wo, v_bias);

    dim3 qvgrid(DM/128, (NB*SEQ)/128, 2);
    qv_gemm512<<<qvgrid, 512, HG_SMEM>>>(query, value, bq, bv);

    dim3 agrid(SEQ/128, NH, NB);
    attn_mma<<<agrid, 256, A_SMEM>>>();

    dim3 ogrid(DM/128, (NB*SEQ)/128);
    o_gemm512<<<ogrid, 512, OG_SMEM>>>(bo, out);
}

// round 15
// speedup vs baseline: 1.0250x; 1.0250x over previous
#include <cuda_runtime.h>
#include <cuda_bf16.h>
#include <cuda_fp16.h>
#include <math.h>
#include <stdint.h>

#define SEQ 1024
#define DM  1024
#define NH  16
#define HD  64
#define NB  2
#define GK  1024
#define L2E 1.4426950408889634f

__device__ __half g_xh[NB*SEQ*DM];
__device__ __half g_vbrelh[NH*2*SEQ + 32];
__device__ __nv_bfloat16 g_qhi[NB*NH*SEQ*HD], g_qlo[NB*NH*SEQ*HD];
__device__ __nv_bfloat16 g_khi[NB*NH*SEQ*HD], g_klo[NB*NH*SEQ*HD];
__device__ __half g_vth[NB*NH*HD*SEQ];
__device__ __nv_bfloat16 g_poshi[(2*SEQ+1)*HD], g_poslo[(2*SEQ+1)*HD];
// pre-split GEMM operands (round-12 proven config)
__device__ __nv_bfloat16 g_qryhi[NB*SEQ*GK], g_qrylo[NB*SEQ*GK];
__device__ __half        g_valh[NB*SEQ*GK];
__device__ __nv_bfloat16 g_wqhi[DM*GK], g_wqlo[DM*GK];
__device__ __half        g_wvhi[DM*GK], g_wvlo[DM*GK];
__device__ __half        g_wohi[DM*GK], g_wolo[DM*GK];

__device__ __forceinline__ uint32_t smem_u32(const void* p) {
    uint32_t a;
    asm("{ .reg .u64 t; cvta.to.shared.u64 t, %1; cvt.u32.u64 %0, t; }" : "=r"(a) : "l"(p));
    return a;
}
__device__ __forceinline__ void ldsm_x4(uint32_t (&r)[4], uint32_t addr) {
    asm volatile("ldmatrix.sync.aligned.m8n8.x4.shared.b16 {%0,%1,%2,%3}, [%4];"
        : "=r"(r[0]), "=r"(r[1]), "=r"(r[2]), "=r"(r[3]) : "r"(addr));
}
__device__ __forceinline__ void mma_bf16(float (&d)[4], const uint32_t (&a)[4],
                                         uint32_t b0, uint32_t b1) {
    asm volatile("mma.sync.aligned.m16n8k16.row.col.f32.bf16.bf16.f32 "
        "{%0,%1,%2,%3}, {%4,%5,%6,%7}, {%8,%9}, {%0,%1,%2,%3};"
        : "+f"(d[0]), "+f"(d[1]), "+f"(d[2]), "+f"(d[3])
        : "r"(a[0]), "r"(a[1]), "r"(a[2]), "r"(a[3]), "r"(b0), "r"(b1));
}
__device__ __forceinline__ void mma_f16(float (&d)[4], const uint32_t (&a)[4],
                                        uint32_t b0, uint32_t b1) {
    asm volatile("mma.sync.aligned.m16n8k16.row.col.f32.f16.f16.f32 "
        "{%0,%1,%2,%3}, {%4,%5,%6,%7}, {%8,%9}, {%0,%1,%2,%3};"
        : "+f"(d[0]), "+f"(d[1]), "+f"(d[2]), "+f"(d[3])
        : "r"(a[0]), "r"(a[1]), "r"(a[2]), "r"(a[3]), "r"(b0), "r"(b1));
}
__device__ __forceinline__ void cpa16(uint32_t dst, const void* src) {
    asm volatile("cp.async.cg.shared.global [%0], [%1], 16;" :: "r"(dst), "l"(src));
}
#define CP_COMMIT() asm volatile("cp.async.commit_group;" ::: "memory")
#define CP_WAIT0()  asm volatile("cp.async.wait_group 0;" ::: "memory")

__device__ __forceinline__ void split_sts(float4 v, char* hi, char* lo) {
    __nv_bfloat162 h01 = __floats2bfloat162_rn(v.x, v.y);
    __nv_bfloat162 h23 = __floats2bfloat162_rn(v.z, v.w);
    float2 f01 = __bfloat1622float2(h01);
    float2 f23 = __bfloat1622float2(h23);
    __nv_bfloat162 l01 = __floats2bfloat162_rn(v.x - f01.x, v.y - f01.y);
    __nv_bfloat162 l23 = __floats2bfloat162_rn(v.z - f23.x, v.w - f23.y);
    *(uint2*)hi = make_uint2(*(uint32_t*)&h01, *(uint32_t*)&h23);
    *(uint2*)lo = make_uint2(*(uint32_t*)&l01, *(uint32_t*)&l23);
}
__device__ __forceinline__ void split_sts_h(float4 v, char* hi, char* lo) {
    __half2 h01 = __floats2half2_rn(v.x, v.y);
    __half2 h23 = __floats2half2_rn(v.z, v.w);
    float2 f01 = __half22float2(h01);
    float2 f23 = __half22float2(h23);
    __half2 l01 = __floats2half2_rn(v.x - f01.x, v.y - f01.y);
    __half2 l23 = __floats2half2_rn(v.z - f23.x, v.w - f23.y);
    *(uint2*)hi = make_uint2(*(uint32_t*)&h01, *(uint32_t*)&h23);
    *(uint2*)lo = make_uint2(*(uint32_t*)&l01, *(uint32_t*)&l23);
}
__device__ __forceinline__ uint32_t packsplit(float a, float b, uint32_t& lo) {
    __nv_bfloat162 hh = __floats2bfloat162_rn(a, b);
    float2 ff = __bfloat1622float2(hh);
    __nv_bfloat162 ll = __floats2bfloat162_rn(a - ff.x, b - ff.y);
    lo = *(uint32_t*)&ll;
    return *(uint32_t*)&hh;
}
__device__ __forceinline__ void split1(float v, __nv_bfloat16& hi, __nv_bfloat16& lo) {
    hi = __float2bfloat16_rn(v);
    lo = __float2bfloat16_rn(v - __bfloat162float(hi));
}

// ---------------- front prep (round-12): pos + vbrel + ALL operand pre-splits ----------------
__global__ __launch_bounds__(512) void front_prep(
    const float* __restrict__ query, const float* __restrict__ keyg,
    const float* __restrict__ value,
    const float* __restrict__ Wq, const float* __restrict__ Wv,
    const float* __restrict__ Wo, const float* __restrict__ vbias)
{
    __shared__ float ps[1024], vbs[1024];
    const int tid = threadIdx.x;
    const int gid = blockIdx.x * 512 + tid;
    const int NT = 256 * 512;

    if (blockIdx.x < 128) {
        const int pid = blockIdx.x;
        for (int i = tid; i < 1024; i += 512) vbs[i] = vbias[i];
        {
            const int li = tid >> 5, j = tid & 31;
            const int l = pid * 16 + li;
            float p = (float)(l - SEQ);
            const double negc = -log(10000.0) / 31.0;
            float ang = p * (float)exp((double)j * negc);
            float s = (float)sin((double)ang), c = (float)cos((double)ang);
            ps[li*64 + j] = s; ps[li*64 + j + 32] = c;
            __nv_bfloat16 hh, ll;
            split1(s, hh, ll); g_poshi[l*64+j] = hh;      g_poslo[l*64+j] = ll;
            split1(c, hh, ll); g_poshi[l*64+j+32] = hh;   g_poslo[l*64+j+32] = ll;
        }
        __syncthreads();
        if (tid < 256) {
            const int li = tid >> 4, h = tid & 15;
            float sum = 0.f;
            #pragma unroll 8
            for (int d = 0; d < 64; d++) sum = fmaf(vbs[h*64+d], ps[li*64+d], sum);
            g_vbrelh[h*2048 + pid*16 + li] = __float2half_rn(sum);
        }
    }

    for (int i = gid; i < 524288; i += NT) {
        float4 v = ((const float4*)query)[i];
        split_sts(v, (char*)g_qryhi + (size_t)i*8, (char*)g_qrylo + (size_t)i*8);
    }
    for (int i = gid; i < 524288; i += NT) {
        float4 v = ((const float4*)keyg)[i];
        int cc = i & 255, ss = (i >> 8) & 1023, bb = i >> 18;
        size_t o = ((size_t)(bb*NH + (cc >> 4))*SEQ + ss)*HD + (cc & 15)*4;
        split_sts(v, (char*)(g_khi + o), (char*)(g_klo + o));
    }
    for (int i = gid; i < 524288; i += NT) {
        float4 v = ((const float4*)value)[i];
        __half2 h0 = __floats2half2_rn(v.x, v.y);
        __half2 h1 = __floats2half2_rn(v.z, v.w);
        *(uint2*)((char*)g_valh + (size_t)i*8) = make_uint2(*(uint32_t*)&h0, *(uint32_t*)&h1);
    }
    for (int i = gid; i < 262144; i += NT) {
        float4 v = ((const float4*)Wq)[i];
        split_sts(v, (char*)g_wqhi + (size_t)i*8, (char*)g_wqlo + (size_t)i*8);
        v = ((const float4*)Wv)[i];
        split_sts_h(v, (char*)g_wvhi + (size_t)i*8, (char*)g_wvlo + (size_t)i*8);
        v = ((const float4*)Wo)[i];
        split_sts_h(v, (char*)g_wohi + (size_t)i*8, (char*)g_wolo + (size_t)i*8);
    }
}

// ---------------- fully-async GEMM cores (round-12) ----------------
#define TSTRIDE 40
#define TILE_B  (128 * TSTRIDE * 2)
#define BUF_B   (4 * TILE_B)
#define HG_SMEM (2 * BUF_B)
#define BUF_H   (3 * TILE_B)
#define OG_SMEM (2 * BUF_H)

__device__ __forceinline__ void gemm3_async(
    const __nv_bfloat16* Ah, const __nv_bfloat16* Al,
    const __nv_bfloat16* Bh, const __nv_bfloat16* Bl,
    uint32_t sbase, int tid, int lane, int wm, int wn, float acc[2][4][4])
{
    const int lr = tid >> 2, lc = (tid & 3) * 8;
    const uint32_t bo = (uint32_t)(lr*TSTRIDE + lc) * 2;
    const int a_r = lane & 15, a_c = (lane >> 4) << 3;
    const int b_r = (lane & 7) + ((lane & 16) >> 1), b_c = lane & 8;

    {
        const size_t o = (size_t)lr*GK + lc;
        cpa16(sbase + bo,            Ah + o);
        cpa16(sbase + TILE_B + bo,   Al + o);
        cpa16(sbase + 2*TILE_B + bo, Bh + o);
        cpa16(sbase + 3*TILE_B + bo, Bl + o);
    }
    CP_COMMIT(); CP_WAIT0(); __syncthreads();

    for (int kt = 0; kt < 32; kt++) {
        if (kt < 31) {
            const size_t o = (size_t)lr*GK + (kt+1)*32 + lc;
            const uint32_t db = sbase + ((kt+1)&1)*BUF_B + bo;
            cpa16(db,            Ah + o);
            cpa16(db + TILE_B,   Al + o);
            cpa16(db + 2*TILE_B, Bh + o);
            cpa16(db + 3*TILE_B, Bl + o);
            CP_COMMIT();
        }
        const uint32_t base = sbase + (kt & 1) * BUF_B;
        #pragma unroll
        for (int kk = 0; kk < 2; kk++) {
            const int koff = kk * 16;
            uint32_t ah[2][4], al[2][4];
            #pragma unroll
            for (int i = 0; i < 2; i++) {
                const uint32_t off = (uint32_t)(((wm*32 + i*16 + a_r)*TSTRIDE + koff + a_c) * 2);
                ldsm_x4(ah[i], base + off);
                ldsm_x4(al[i], base + TILE_B + off);
            }
            uint32_t bh[2][4], bl[2][4];
            #pragma unroll
            for (int p = 0; p < 2; p++) {
                const uint32_t off = (uint32_t)(((wn*32 + p*16 + b_r)*TSTRIDE + koff + b_c) * 2);
                ldsm_x4(bh[p], base + 2*TILE_B + off);
                ldsm_x4(bl[p], base + 3*TILE_B + off);
            }
            #pragma unroll
            for (int i = 0; i < 2; i++)
                #pragma unroll
                for (int j = 0; j < 4; j++) {
                    const int p = j >> 1, s = (j & 1) * 2;
                    mma_bf16(acc[i][j], ah[i], bh[p][s], bh[p][s+1]);
                    mma_bf16(acc[i][j], ah[i], bl[p][s], bl[p][s+1]);
                    mma_bf16(acc[i][j], al[i], bh[p][s], bh[p][s+1]);
                }
        }
        if (kt < 31) { CP_WAIT0(); __syncthreads(); }
    }
}

__device__ __forceinline__ void gemm2h_async(
    const __half* Ax, const __half* Bh, const __half* Bl,
    uint32_t sbase, int tid, int lane, int wm, int wn, float acc[2][4][4])
{
    const int lr = tid >> 2, lc = (tid & 3) * 8;
    const uint32_t bo = (uint32_t)(lr*TSTRIDE + lc) * 2;
    const int a_r = lane & 15, a_c = (lane >> 4) << 3;
    const int b_r = (lane & 7) + ((lane & 16) >> 1), b_c = lane & 8;

    {
        const size_t o = (size_t)lr*GK + lc;
        cpa16(sbase + bo,            Ax + o);
        cpa16(sbase + TILE_B + bo,   Bh + o);
        cpa16(sbase + 2*TILE_B + bo, Bl + o);
    }
    CP_COMMIT(); CP_WAIT0(); __syncthreads();

    for (int kt = 0; kt < 32; kt++) {
        if (kt < 31) {
            const size_t o = (size_t)lr*GK + (kt+1)*32 + lc;
            const uint32_t db = sbase + ((kt+1)&1)*BUF_H + bo;
            cpa16(db,            Ax + o);
            cpa16(db + TILE_B,   Bh + o);
            cpa16(db + 2*TILE_B, Bl + o);
            CP_COMMIT();
        }
        const uint32_t base = sbase + (kt & 1) * BUF_H;
        #pragma unroll
        for (int kk = 0; kk < 2; kk++) {
            const int koff = kk * 16;
            uint32_t af[2][4];
            #pragma unroll
            for (int i = 0; i < 2; i++) {
                const uint32_t off = (uint32_t)(((wm*32 + i*16 + a_r)*TSTRIDE + koff + a_c) * 2);
                ldsm_x4(af[i], base + off);
            }
            uint32_t bh[2][4], bl[2][4];
            #pragma unroll
            for (int p = 0; p < 2; p++) {
                const uint32_t off = (uint32_t)(((wn*32 + p*16 + b_r)*TSTRIDE + koff + b_c) * 2);
                ldsm_x4(bh[p], base + TILE_B + off);
                ldsm_x4(bl[p], base + 2*TILE_B + off);
            }
            #pragma unroll
            for (int i = 0; i < 2; i++)
                #pragma unroll
                for (int j = 0; j < 4; j++) {
                    const int p = j >> 1, s = (j & 1) * 2;
                    mma_f16(acc[i][j], af[i], bh[p][s], bh[p][s+1]);
                    mma_f16(acc[i][j], af[i], bl[p][s], bl[p][s+1]);
                }
        }
        if (kt < 31) { CP_WAIT0(); __syncthreads(); }
    }
}

// z=0: Q proj; z=1: V proj (transposed fp16 out)
__global__ __launch_bounds__(512) void qv_gemm512(
    const float* __restrict__ bq, const float* __restrict__ bv)
{
    extern __shared__ __align__(16) char smraw[];
    const int tid = threadIdx.x, lane = tid & 31, wid = tid >> 5;
    const int wm = wid & 3, wn = wid >> 2;
    const int row0 = blockIdx.y * 128, col0 = blockIdx.x * 128;
    const int z = blockIdx.z;

    float acc[2][4][4];
    #pragma unroll
    for (int i = 0; i < 2; i++)
        #pragma unroll
        for (int j = 0; j < 4; j++)
            #pragma unroll
            for (int c = 0; c < 4; c++) acc[i][j][c] = 0.f;

    const int grp = lane >> 2, qid = lane & 3;
    const uint32_t sb = smem_u32(smraw);

    if (z == 0) {
        gemm3_async(g_qryhi + (size_t)row0*GK, g_qrylo + (size_t)row0*GK,
                    g_wqhi + (size_t)col0*GK,  g_wqlo + (size_t)col0*GK,
                    sb, tid, lane, wm, wn, acc);
        #pragma unroll
        for (int j = 0; j < 4; j++) {
            const int col = col0 + wn*32 + j*8 + qid*2;
            const float2 bj = *(const float2*)(bq + col);
            const int h = col >> 6, d = col & 63;
            #pragma unroll
            for (int i = 0; i < 2; i++) {
                const int row = row0 + wm*32 + i*16 + grp;
                const int b = row >> 10, s = row & 1023;
                size_t o = (((size_t)(b*NH + h))*SEQ + s)*HD + d;
                uint32_t lo0, lo1;
                uint32_t hi0 = packsplit(acc[i][j][0]+bj.x, acc[i][j][1]+bj.y, lo0);
                uint32_t hi1 = packsplit(acc[i][j][2]+bj.x, acc[i][j][3]+bj.y, lo1);
                *(uint32_t*)(g_qhi + o) = hi0;        *(uint32_t*)(g_qlo + o) = lo0;
                *(uint32_t*)(g_qhi + o + 8*HD) = hi1; *(uint32_t*)(g_qlo + o + 8*HD) = lo1;
            }
        }
    } else {
        gemm2h_async(g_valh + (size_t)row0*GK,
                     g_wvhi + (size_t)col0*GK, g_wvlo + (size_t)col0*GK,
                     sb, tid, lane, wm, wn, acc);
        #pragma unroll
        for (int j = 0; j < 4; j++) {
            const int col = col0 + wn*32 + j*8 + qid*2;
            const float2 bj = *(const float2*)(bv + col);
            const int h = col >> 6, d = col & 63;
            #pragma unroll
            for (int i = 0; i < 2; i++) {
                const int row = row0 + wm*32 + i*16 + grp;
                const int b = row >> 10, s = row & 1023;
                size_t o = (((size_t)(b*NH + h))*HD + d)*SEQ + s;
                g_vth[o]        = __float2half_rn(acc[i][j][0]+bj.x);
                g_vth[o+SEQ]    = __float2half_rn(acc[i][j][1]+bj.y);
                g_vth[o+8]      = __float2half_rn(acc[i][j][2]+bj.x);
                g_vth[o+SEQ+8]  = __float2half_rn(acc[i][j][3]+bj.y);
            }
        }
    }
}

__global__ __launch_bounds__(512) void o_gemm512(
    const float* __restrict__ bias, float* __restrict__ C)
{
    extern __shared__ __align__(16) char smraw[];
    const int tid = threadIdx.x, lane = tid & 31, wid = tid >> 5;
    const int wm = wid & 3, wn = wid >> 2;
    const int row0 = blockIdx.y * 128, col0 = blockIdx.x * 128;

    float acc[2][4][4];
    #pragma unroll
    for (int i = 0; i < 2; i++)
        #pragma unroll
        for (int j = 0; j < 4; j++)
            #pragma unroll
            for (int c = 0; c < 4; c++) acc[i][j][c] = 0.f;

    gemm2h_async(g_xh + (size_t)row0*GK,
                 g_wohi + (size_t)col0*GK, g_wolo + (size_t)col0*GK,
                 smem_u32(smraw), tid, lane, wm, wn, acc);

    const int grp = lane >> 2, qid = lane & 3;
    #pragma unroll
    for (int j = 0; j < 4; j++) {
        const int col = col0 + wn*32 + j*8 + qid*2;
        const float2 bj = *(const float2*)(bias + col);
        #pragma unroll
        for (int i = 0; i < 2; i++) {
            const int row = row0 + wm*32 + i*16 + grp;
            *(float2*)(C + (size_t)row*DM + col)     = make_float2(acc[i][j][0]+bj.x, acc[i][j][1]+bj.y);
            *(float2*)(C + (size_t)(row+8)*DM + col) = make_float2(acc[i][j][2]+bj.x, acc[i][j][3]+bj.y);
        }
    }
}

// --------- pipelined tensor-core fused attention (round-14: ex2 + smem vbrel) ---------
#define RSTR 130
#define S0OFF 32768u
#define S1OFF 65536u
#define ROFF  98304
#define RSLOT 66560
#define VBOFF 231424u
#define A_SMEM 231936

__device__ __forceinline__ void stage_rows_async(
    uint32_t sb, uint32_t so, int tid,
    const __nv_bfloat16* hp, const __nv_bfloat16* lp)
{
    #pragma unroll
    for (int r = 0; r < 4; r++) {
        int idx = tid + r*256, row = idx >> 3, c = idx & 7;
        uint32_t off = so + row*128 + ((c ^ (row & 7)) << 4);
        cpa16(sb + off,         (const char*)hp + idx*16);
        cpa16(sb + off + 16384, (const char*)lp + idx*16);
    }
}
__device__ __forceinline__ void stage_vb_scalar(char* sm, int slot, int tid, const __half* src) {
    if (tid < 128) ((__half*)(sm + VBOFF))[slot*128 + tid] = __ldg(src + tid);
}
__device__ __forceinline__ void stage_vt_async(
    uint32_t sb, uint32_t so, int tid, const __half* hp, int k0)
{
    #pragma unroll
    for (int r = 0; r < 4; r++) {
        int idx = tid + r*256, d = idx >> 4, c = idx & 15;
        uint32_t off = so + d*256 + ((c ^ (d & 7)) << 4);
        cpa16(sb + off, (const char*)(hp + (size_t)d*SEQ + k0) + c*16);
    }
}

__device__ __forceinline__ void rgemm_band(
    uint32_t sb, uint32_t so, int lane, int wm, int wn, int grp, int qid,
    float* R, const __half* vbs)
{
    float rc[4][4][4];
    #pragma unroll
    for (int i = 0; i < 4; i++)
        #pragma unroll
        for (int j = 0; j < 4; j++) { rc[i][j][0]=0;rc[i][j][1]=0;rc[i][j][2]=0;rc[i][j][3]=0; }
    #pragma unroll
    for (int kb = 0; kb < 4; kb++) {
        uint32_t ah[4][4], al[4][4];
        #pragma unroll
        for (int i = 0; i < 4; i++) {
            uint32_t ao = (uint32_t)((wm*64 + i*16 + (lane&15))*128
                         + (((kb*2 + (lane>>4)) ^ (lane&7)) << 4));
            ldsm_x4(ah[i], sb + ao);
            ldsm_x4(al[i], sb + 16384 + ao);
        }
        uint32_t bh2[2][4], bl2[2][4];
        #pragma unroll
        for (int jp = 0; jp < 2; jp++) {
            uint32_t bo = (uint32_t)((wn*32 + jp*16 + (lane&7) + ((lane&16)>>1))*128
                         + (((kb*2 + ((lane&8)>>3)) ^ (lane&7)) << 4));
            ldsm_x4(bh2[jp], sb + so + bo);
            ldsm_x4(bl2[jp], sb + so + 16384 + bo);
        }
        #pragma unroll
        for (int i = 0; i < 4; i++)
            #pragma unroll
            for (int j = 0; j < 4; j++) {
                const int jp = j >> 1, s = (j & 1)*2;
                mma_bf16(rc[i][j], ah[i], bh2[jp][s], bh2[jp][s+1]);
                mma_bf16(rc[i][j], ah[i], bl2[jp][s], bl2[jp][s+1]);
                mma_bf16(rc[i][j], al[i], bh2[jp][s], bh2[jp][s+1]);
            }
    }
    #pragma unroll
    for (int i = 0; i < 4; i++) {
        const int u = wm*64 + i*16 + grp;
        #pragma unroll
        for (int j = 0; j < 4; j++) {
            const int l = wn*32 + j*8 + qid*2;
            float2 vf = __half22float2(*(const __half2*)(vbs + l));
            *(float2*)&R[u*RSTR + l]     = make_float2(rc[i][j][0]+vf.x, rc[i][j][1]+vf.y);
            *(float2*)&R[(u+8)*RSTR + l] = make_float2(rc[i][j][2]+vf.x, rc[i][j][3]+vf.y);
        }
    }
}

__global__ __launch_bounds__(256, 1) void attn_mma()
{
    extern __shared__ __align__(16) char sm[];
    float* Rb0 = (float*)(sm + ROFF);
    float* Rb1 = (float*)(sm + ROFF + RSLOT);
    const __half* vb0 = (const __half*)(sm + VBOFF);
    const __half* vb1 = (const __half*)(sm + VBOFF + 256);
    const int tid = threadIdx.x, lane = tid & 31, wid = tid >> 5;
    const int grp = lane >> 2, qid = lane & 3;
    const int q0 = blockIdx.x*128, h = blockIdx.y, b = blockIdx.z, bh = b*NH + h;
    const uint32_t sb = smem_u32(sm);
    const int wm = wid & 1, wn = wid >> 1;
    const int u0w = wid*16, r0 = u0w + grp;
    const int lmin0 = SEQ - q0 - 127;
    const __half* vbgh = g_vbrelh + h*2048;
    const __nv_bfloat16* khB = g_khi + (size_t)bh*SEQ*HD;
    const __nv_bfloat16* klB = g_klo + (size_t)bh*SEQ*HD;
    const __half* vhB = g_vth + (size_t)bh*HD*SEQ;

    {   // Q stage (sync, once)
        const uint4* sh = (const uint4*)(g_qhi + ((size_t)bh*SEQ + q0)*HD);
        const uint4* sl = (const uint4*)(g_qlo + ((size_t)bh*SEQ + q0)*HD);
        #pragma unroll
        for (int r = 0; r < 4; r++) {
            int idx = tid + r*256, row = idx >> 3, c = idx & 7;
            int off = row*128 + ((c ^ (row & 7)) << 4);
            *(uint4*)(sm + off) = sh[idx];
            *(uint4*)(sm + 16384 + off) = sl[idx];
        }
    }
    float O[8][4];
    #pragma unroll
    for (int j = 0; j < 8; j++) { O[j][0]=0;O[j][1]=0;O[j][2]=0;O[j][3]=0; }
    float mr0 = -INFINITY, mr1 = -INFINITY, lr0 = 0.f, lr1 = 0.f;

    // prologue
    stage_rows_async(sb, S0OFF, tid, g_poshi + (size_t)lmin0*HD, g_poslo + (size_t)lmin0*HD);
    stage_vb_scalar(sm, 0, tid, vbgh + lmin0);
    CP_COMMIT(); CP_WAIT0(); __syncthreads();

    stage_rows_async(sb, S1OFF, tid, g_poshi + (size_t)(lmin0+128)*HD, g_poslo + (size_t)(lmin0+128)*HD);
    stage_vb_scalar(sm, 1, tid, vbgh + lmin0 + 128);
    CP_COMMIT();
    rgemm_band(sb, S0OFF, lane, wm, wn, grp, qid, Rb0, vb0);
    CP_WAIT0(); __syncthreads();

    stage_rows_async(sb, S0OFF, tid, khB, klB);
    CP_COMMIT();
    rgemm_band(sb, S1OFF, lane, wm, wn, grp, qid, Rb1, vb1);
    CP_WAIT0(); __syncthreads();

    for (int kt = 0; kt < 8; kt++) {
        const int k0 = kt*128;
        const uint32_t kOff = (kt & 1) ? S1OFF : S0OFF;
        const uint32_t vOff = (kt & 1) ? S0OFF : S1OFF;

        if (kt > 0) {
            stage_rows_async(sb, kOff, tid, khB + (size_t)k0*HD, klB + (size_t)k0*HD);
            CP_COMMIT();
            rgemm_band(sb, vOff, lane, wm, wn, grp, qid,
                       ((kt+1) & 1) ? Rb1 : Rb0, ((kt+1) & 1) ? vb1 : vb0);
            CP_WAIT0(); __syncthreads();
        }

        stage_vt_async(sb, vOff, tid, vhB, k0);
        CP_COMMIT();

        float aq[16][4];
        #pragma unroll
        for (int j = 0; j < 16; j++) { aq[j][0]=0;aq[j][1]=0;aq[j][2]=0;aq[j][3]=0; }
        #pragma unroll
        for (int kb = 0; kb < 4; kb++) {
            uint32_t ah[4], al[4];
            uint32_t ao = (uint32_t)((u0w + (lane&15))*128
                         + (((kb*2 + (lane>>4)) ^ (lane&7)) << 4));
            ldsm_x4(ah, sb + ao);
            ldsm_x4(al, sb + 16384 + ao);
            #pragma unroll
            for (int jp = 0; jp < 8; jp++) {
                uint32_t bh4[4], bl4[4];
                uint32_t bo = (uint32_t)((jp*16 + (lane&7) + ((lane&16)>>1))*128
                             + (((kb*2 + ((lane&8)>>3)) ^ (lane&7)) << 4));
                ldsm_x4(bh4, sb + kOff + bo);
                ldsm_x4(bl4, sb + kOff + 16384 + bo);
                #pragma unroll
                for (int jj = 0; jj < 2; jj++) {
                    const int j = jp*2 + jj, s = jj*2;
                    mma_bf16(aq[j], ah, bh4[s], bh4[s+1]);
                    mma_bf16(aq[j], ah, bl4[s], bl4[s+1]);
                    mma_bf16(aq[j], al, bh4[s], bh4[s+1]);
                }
            }
        }

        CP_WAIT0(); __syncthreads();
        if (kt < 7) {
            const int l0n = lmin0 + 128*(kt+2);
            stage_rows_async(sb, kOff, tid, g_poshi + (size_t)l0n*HD, g_poslo + (size_t)l0n*HD);
            stage_vb_scalar(sm, kt & 1, tid, vbgh + l0n);
            CP_COMMIT();
        }

        const float* RA  = (kt & 1) ? Rb1 : Rb0;
        const float* RBf = (kt & 1) ? Rb0 : Rb1;
        float m0 = -INFINITY, m1 = -INFINITY;
        #pragma unroll
        for (int j = 0; j < 16; j++) {
            const int w = j*8 + qid*2;
            const int ma = 127 + w - r0, mb = ma - 8;
            aq[j][0] += (ma < 128)   ? RA[r0*RSTR + ma]         : RBf[r0*RSTR + ma - 128];
            aq[j][1] += (ma+1 < 128) ? RA[r0*RSTR + ma + 1]     : RBf[r0*RSTR + ma - 127];
            aq[j][2] += (mb < 128)   ? RA[(r0+8)*RSTR + mb]     : RBf[(r0+8)*RSTR + mb - 128];
            aq[j][3] += (mb+1 < 128) ? RA[(r0+8)*RSTR + mb + 1] : RBf[(r0+8)*RSTR + mb - 127];
            m0 = fmaxf(m0, fmaxf(aq[j][0], aq[j][1]));
            m1 = fmaxf(m1, fmaxf(aq[j][2], aq[j][3]));
        }
        m0 = fmaxf(m0, __shfl_xor_sync(~0u, m0, 1));
        m0 = fmaxf(m0, __shfl_xor_sync(~0u, m0, 2));
        m1 = fmaxf(m1, __shfl_xor_sync(~0u, m1, 1));
        m1 = fmaxf(m1, __shfl_xor_sync(~0u, m1, 2));
        const float mn0 = fmaxf(mr0, m0), mn1 = fmaxf(mr1, m1);
        const float scl0 = __expf(mr0 - mn0), scl1 = __expf(mr1 - mn1);
        mr0 = mn0; mr1 = mn1;

        uint32_t phi[8][4];
        float s0 = 0.f, s1 = 0.f;
        #pragma unroll
        for (int j = 0; j < 16; j++) {
            __half2 hd0 = __floats2half2_rn((aq[j][0]-mn0)*L2E, (aq[j][1]-mn0)*L2E);
            __half2 hd1 = __floats2half2_rn((aq[j][2]-mn1)*L2E, (aq[j][3]-mn1)*L2E);
            uint32_t p0, p1;
            asm("ex2.approx.f16x2 %0, %1;" : "=r"(p0) : "r"(*(uint32_t*)&hd0));
            asm("ex2.approx.f16x2 %0, %1;" : "=r"(p1) : "r"(*(uint32_t*)&hd1));
            const int kk = j >> 1, bs = (j & 1)*2;
            phi[kk][bs]   = p0;
            phi[kk][bs+1] = p1;
            float2 f0 = __half22float2(*(__half2*)&p0);
            float2 f1 = __half22float2(*(__half2*)&p1);
            s0 += f0.x + f0.y; s1 += f1.x + f1.y;
        }
        s0 += __shfl_xor_sync(~0u, s0, 1); s0 += __shfl_xor_sync(~0u, s0, 2);
        s1 += __shfl_xor_sync(~0u, s1, 1); s1 += __shfl_xor_sync(~0u, s1, 2);
        lr0 = lr0*scl0 + s0; lr1 = lr1*scl1 + s1;
        #pragma unroll
        for (int j = 0; j < 8; j++) {
            O[j][0] *= scl0; O[j][1] *= scl0; O[j][2] *= scl1; O[j][3] *= scl1;
        }

        // PV immediately (no barrier)
        #pragma unroll
        for (int kk = 0; kk < 8; kk++) {
            #pragma unroll
            for (int jp = 0; jp < 4; jp++) {
                uint32_t bh4[4];
                uint32_t bo = (uint32_t)((jp*16 + (lane&7) + ((lane&16)>>1))*256
                             + (((kk*2 + ((lane&8)>>3)) ^ (lane&7)) << 4));
                ldsm_x4(bh4, sb + vOff + bo);
                mma_f16(O[jp*2],   phi[kk], bh4[0], bh4[1]);
                mma_f16(O[jp*2+1], phi[kk], bh4[2], bh4[3]);
            }
        }
        if (kt < 7) CP_WAIT0();
        __syncthreads();
    }

    const float i0 = 1.f/lr0, i1 = 1.f/lr1;
    __half* x0 = g_xh + ((size_t)(b*SEQ + q0 + r0))*DM + h*HD;
    __half* x1 = g_xh + ((size_t)(b*SEQ + q0 + r0 + 8))*DM + h*HD;
    #pragma unroll
    for (int j = 0; j < 8; j++) {
        const int col = j*8 + qid*2;
        __half2 o0 = __floats2half2_rn(O[j][0]*i0, O[j][1]*i0);
        __half2 o1 = __floats2half2_rn(O[j][2]*i1, O[j][3]*i1);
        *(__half2*)(x0 + col) = o0;
        *(__half2*)(x1 + col) = o1;
    }
}

// ---------------------------------------------------------------------------
extern "C" void kernel_launch(void* const* d_in, const int* in_sizes, int n_in,
                              void* d_out, int out_size) {
    const float* query  = (const float*)d_in[0];
    const float* key    = (const float*)d_in[1];
    const float* value  = (const float*)d_in[2];
    const float* Wq     = (const float*)d_in[4];
    const float* bq     = (const float*)d_in[5];
    const float* Wv     = (const float*)d_in[6];
    const float* bv     = (const float*)d_in[7];
    const float* Wo     = (const float*)d_in[8];
    const float* bo     = (const float*)d_in[9];
    const float* v_bias = (const float*)d_in[10];
    float* out = (float*)d_out;

    cudaFuncSetAttribute(qv_gemm512, cudaFuncAttributeMaxDynamicSharedMemorySize, HG_SMEM);
    cudaFuncSetAttribute(o_gemm512, cudaFuncAttributeMaxDynamicSharedMemorySize, OG_SMEM);
    cudaFuncSetAttribute(attn_mma, cudaFuncAttributeMaxDynamicSharedMemorySize, A_SMEM);

    front_prep<<<256, 512>>>(query, key, value, Wq, Wv, Wo, v_bias);

    dim3 qvgrid(DM/128, (NB*SEQ)/128, 2);
    qv_gemm512<<<qvgrid, 512, HG_SMEM>>>(bq, bv);

    dim3 agrid(SEQ/128, NH, NB);
    attn_mma<<<agrid, 256, A_SMEM>>>();

    dim3 ogrid(DM/128, (NB*SEQ)/128);
    o_gemm512<<<ogrid, 512, OG_SMEM>>>(bo, out);
}